// round 6
// baseline (speedup 1.0000x reference)
#include <cuda_runtime.h>
#include <cstdint>

// Problem constants
#define T_STEPS 512
#define HDIM    128
#define G4      512     // 4*H
#define OUTD    64
#define BSEL    255     // only batch row that affects the output
#define HHALF   72      // 64 floats + 8 pad per half
#define HBUFP   (2 * HHALF)   // one parity buffer = 144 floats

// ---------------- scratch (no allocations allowed) ----------------
__device__ float g_xg[T_STEPS * G4];     // precomputed input gates for batch 255
__device__ float g_hout[256 * HDIM];     // h[255, 256+j, :]
__device__ float g_Wc[OUTD * HDIM];      // W2 @ W1
__device__ float g_bc[OUTD];             // W2 @ b1 + b2

// ---------------- helpers ----------------
__device__ __forceinline__ float fast_sigmoid(float x) {
    return 1.0f / (1.0f + __expf(-x));
}
__device__ __forceinline__ float fast_tanh(float x) {
    return 1.0f - 2.0f / (__expf(2.0f * x) + 1.0f);
}
__device__ __forceinline__ void fma_f32x2(unsigned long long& acc,
                                          unsigned long long a,
                                          unsigned long long b) {
    asm("fma.rn.f32x2 %0, %1, %2, %0;" : "+l"(acc) : "l"(a), "l"(b));
}
__device__ __forceinline__ unsigned long long add_f32x2(unsigned long long a,
                                                        unsigned long long b) {
    unsigned long long r;
    asm("add.rn.f32x2 %0, %1, %2;" : "=l"(r) : "l"(a), "l"(b));
    return r;
}
__device__ __forceinline__ uint32_t smem_u32(const void* p) {
    uint32_t a;
    asm("{ .reg .u64 t; cvta.to.shared.u64 t, %1; cvt.u32.u64 %0, t; }"
        : "=r"(a) : "l"(p));
    return a;
}
#define CLUSTER_SYNC() do { \
    asm volatile("barrier.cluster.arrive.aligned;" ::: "memory"); \
    asm volatile("barrier.cluster.wait.aligned;"   ::: "memory"); \
} while (0)

__device__ __forceinline__ void mbar_init(uint32_t mbar, uint32_t count) {
    asm volatile("mbarrier.init.shared.b64 [%0], %1;" :: "r"(mbar), "r"(count) : "memory");
}
__device__ __forceinline__ void mbar_arrive_remote(uint32_t mbar) {
    asm volatile("mbarrier.arrive.release.cluster.shared::cluster.b64 _, [%0];"
                 :: "r"(mbar) : "memory");
}
__device__ __forceinline__ void mbar_wait_parity_cluster(uint32_t mbar, uint32_t parity) {
    asm volatile(
        "{\n\t"
        ".reg .pred P;\n"
        "WL%=:\n\t"
        "mbarrier.try_wait.parity.acquire.cluster.shared::cta.b64 P, [%0], %1;\n\t"
        "@P bra.uni WD%=;\n\t"
        "bra.uni WL%=;\n"
        "WD%=:\n\t"
        "}"
        :: "r"(mbar), "r"(parity) : "memory");
}

// ---------------- kernel 1: xg[t, j] = W_ih[j,:] . x[255,t,:] + b_ih[j] + b_hh[j]
__global__ void __launch_bounds__(512) xg_kernel(
    const float* __restrict__ x, const float* __restrict__ Wih,
    const float* __restrict__ bih, const float* __restrict__ bhh)
{
    __shared__ __align__(16) float xs[8][HDIM];
    int t0 = blockIdx.x * 8;
    int j  = threadIdx.x;

    for (int i = j; i < 8 * HDIM; i += 512) {
        int tt = i >> 7, d = i & 127;
        xs[tt][d] = x[((size_t)BSEL * T_STEPS + t0 + tt) * HDIM + d];
    }
    __syncthreads();

    const float4* wr4 = reinterpret_cast<const float4*>(Wih + j * HDIM);
    float acc[8];
    #pragma unroll
    for (int tt = 0; tt < 8; tt++) acc[tt] = 0.0f;

    #pragma unroll
    for (int q = 0; q < HDIM / 4; q++) {
        float4 w = wr4[q];
        #pragma unroll
        for (int tt = 0; tt < 8; tt++) {
            float4 xv = reinterpret_cast<const float4*>(xs[tt])[q];
            acc[tt] += w.x * xv.x + w.y * xv.y + w.z * xv.z + w.w * xv.w;
        }
    }
    float bb = bih[j] + bhh[j];
    #pragma unroll
    for (int tt = 0; tt < 8; tt++)
        g_xg[(t0 + tt) * G4 + j] = acc[tt] + bb;
}

// ---------------- kernel 2: collapse the two affine layers
__global__ void __launch_bounds__(512) mlp_precomp_kernel(
    const float* __restrict__ W1, const float* __restrict__ b1,
    const float* __restrict__ W2, const float* __restrict__ b2)
{
    int idx = blockIdx.x * blockDim.x + threadIdx.x;
    if (idx < OUTD * HDIM) {
        int o = idx >> 7, hh = idx & 127;
        float acc = 0.0f;
        #pragma unroll 4
        for (int m = 0; m < HDIM; m++)
            acc += W2[o * HDIM + m] * W1[m * HDIM + hh];
        g_Wc[idx] = acc;
    }
    if (idx < OUTD) {
        float acc = b2[idx];
        #pragma unroll 4
        for (int m = 0; m < HDIM; m++)
            acc += W2[idx * HDIM + m] * b1[m];
        g_bc[idx] = acc;
    }
}

// ---------------- kernel 3: sequential LSTM scan (batch 255 only)
// 2-CTA cluster, 256 threads each. Thread tid: q = tid&3, eL = tid>>2,
// element e = rank*64+eL. Each thread owns all 4 gate rows of e over
// 16 LOCAL columns (rank*64+16q..+15) and 16 REMOTE columns
// ((rank^1)*64+16q..+15); weights in registers (64 u64).
// Per step: phase A (local-half dot) runs BEFORE the remote wait, hiding the
// DSMEM fabric latency; phase B (remote-half) after. Sync = per-warp elected
// mbarrier arrive.release.cluster (8 arrives/step, count=8) + parity wait.
__global__ void __cluster_dims__(2, 1, 1) __launch_bounds__(256, 1)
lstm_scan_kernel(const float* __restrict__ Whh)
{
    __shared__ __align__(16) float h_smem[2 * HBUFP];  // [parity][half][HHALF]
    __shared__ __align__(8) unsigned long long bar_storage;

    int tid = threadIdx.x;
    unsigned rank;
    asm("mov.u32 %0, %%cluster_ctarank;" : "=r"(rank));

    int q  = tid & 3;
    int eL = tid >> 2;
    int e  = (int)rank * 64 + eL;

    int colL = (int)rank * 64 + q * 16;          // local 16 columns
    int colR = (int)(rank ^ 1u) * 64 + q * 16;   // remote 16 columns

    // register-resident weights: 4 gates x (8 local + 8 remote) u64
    unsigned long long wA[4][8], wB[4][8];
    #pragma unroll
    for (int g = 0; g < 4; g++) {
        const unsigned long long* row = reinterpret_cast<const unsigned long long*>(
            Whh + (size_t)(g * HDIM + e) * HDIM);
        #pragma unroll
        for (int k = 0; k < 8; k++) {
            wA[g][k] = row[colL / 2 + k];
            wB[g][k] = row[colR / 2 + k];
        }
    }

    uint32_t lbar = smem_u32(&bar_storage);
    uint32_t rbar;
    asm("mapa.shared::cluster.u32 %0, %1, %2;" : "=r"(rbar) : "r"(lbar), "r"(rank ^ 1u));
    uint32_t hbase = smem_u32(h_smem);
    uint32_t rhbase;
    asm("mapa.shared::cluster.u32 %0, %1, %2;" : "=r"(rhbase) : "r"(hbase), "r"(rank ^ 1u));

    if (tid == 0) mbar_init(lbar, 8);
    // zero parity-0 buffer (both halves; zeros need no exchange)
    if (tid < HBUFP) h_smem[tid] = 0.0f;
    __syncthreads();
    CLUSTER_SYNC();   // mbarrier init + zeroed buffers visible cluster-wide

    // prologue: complete peer's phase 0 (remote zeros are already in place)
    if ((tid & 31) == 0) mbar_arrive_remote(rbar);

    bool writer = (q == 0);
    uint32_t woff = (uint32_t)((rank * HHALF + eL) * 4); // my element's slot (byte)

    float c = 0.0f;                           // redundant across the 4 lanes
    const float* xg_base = g_xg + q * HDIM + e;

    for (int t = 0; t < T_STEPS; t++) {
        int p = t & 1;
        float xgv = __ldg(xg_base + t * G4);

        // ---- phase A: local-half partial dots (data valid since last syncthreads)
        const ulonglong2* hpA = reinterpret_cast<const ulonglong2*>(
            h_smem + p * HBUFP + rank * HHALF + q * 16);
        unsigned long long hA[8];
        #pragma unroll
        for (int k = 0; k < 4; k++) {
            ulonglong2 v = hpA[k];
            hA[2 * k] = v.x; hA[2 * k + 1] = v.y;
        }
        float pacc[4];
        #pragma unroll
        for (int g = 0; g < 4; g++) {
            unsigned long long a0 = 0ull, a1 = 0ull;
            #pragma unroll
            for (int k = 0; k < 8; k += 2) {
                fma_f32x2(a0, wA[g][k],     hA[k]);
                fma_f32x2(a1, wA[g][k + 1], hA[k + 1]);
            }
            unsigned long long s = add_f32x2(a0, a1);
            float sx, sy;
            asm("mov.b64 {%0,%1}, %2;" : "=f"(sx), "=f"(sy) : "l"(s));
            pacc[g] = sx + sy;
        }
        pacc[q] += xgv;

        // ---- wait for peer's h (fabric latency overlapped with phase A)
        mbar_wait_parity_cluster(lbar, (uint32_t)p);

        // ---- phase B: remote-half partial dots
        const ulonglong2* hpB = reinterpret_cast<const ulonglong2*>(
            h_smem + p * HBUFP + (rank ^ 1u) * HHALF + q * 16);
        unsigned long long hB[8];
        #pragma unroll
        for (int k = 0; k < 4; k++) {
            ulonglong2 v = hpB[k];
            hB[2 * k] = v.x; hB[2 * k + 1] = v.y;
        }
        #pragma unroll
        for (int g = 0; g < 4; g++) {
            unsigned long long a0 = 0ull, a1 = 0ull;
            #pragma unroll
            for (int k = 0; k < 8; k += 2) {
                fma_f32x2(a0, wB[g][k],     hB[k]);
                fma_f32x2(a1, wB[g][k + 1], hB[k + 1]);
            }
            unsigned long long s = add_f32x2(a0, a1);
            float sx, sy;
            asm("mov.b64 {%0,%1}, %2;" : "=f"(sx), "=f"(sy) : "l"(s));
            pacc[g] += sx + sy;
        }

        // ---- butterfly-reduce the 4-lane group
        #pragma unroll
        for (int g = 0; g < 4; g++) pacc[g] += __shfl_xor_sync(0xFFFFFFFFu, pacc[g], 1);
        #pragma unroll
        for (int g = 0; g < 4; g++) pacc[g] += __shfl_xor_sync(0xFFFFFFFFu, pacc[g], 2);

        // ---- gate math (redundant in all 4 lanes)
        float iv = fast_sigmoid(pacc[0]);
        float fv = fast_sigmoid(pacc[1]);
        float gv = fast_tanh(pacc[2]);
        float ov = fast_sigmoid(pacc[3]);
        c = fv * c + iv * gv;
        float h = ov * fast_tanh(c);

        uint32_t off = (uint32_t)(((t + 1) & 1) * (HBUFP * 4)) + woff;
        if (writer) {
            asm volatile("st.shared.f32 [%0], %1;"
                         :: "r"(hbase + off), "f"(h) : "memory");
            asm volatile("st.shared::cluster.f32 [%0], %1;"
                         :: "r"(rhbase + off), "f"(h) : "memory");
            if (t >= 256) g_hout[(t - 256) * HDIM + e] = h;
        }
        // warp-local ordering of the 8 writers' stores, then one elected
        // release-arrive per warp on the PEER's barrier (8 arrives = phase t+1)
        __syncwarp();
        if ((tid & 31) == 0) mbar_arrive_remote(rbar);
        // local visibility of buf[(t+1)&1][rank] for next step's phase A
        __syncthreads();
    }
    CLUSTER_SYNC();   // keep smem/barrier alive until the peer is done
}

// ---------------- kernel 4: out[j, o] = bc[o] + Wc[o,:] . h[255, 256+j, :]
__global__ void __launch_bounds__(64) mlp_final_kernel(float* __restrict__ out)
{
    __shared__ __align__(16) float hs[HDIM];
    int j = blockIdx.x;
    int o = threadIdx.x;
    hs[o]      = g_hout[j * HDIM + o];
    hs[o + 64] = g_hout[j * HDIM + 64 + o];
    __syncthreads();

    const float4* wr4 = reinterpret_cast<const float4*>(g_Wc + o * HDIM);
    float a0 = 0.0f, a1 = 0.0f;
    #pragma unroll
    for (int qq = 0; qq < HDIM / 4; qq += 2) {
        float4 w0 = wr4[qq],     x0 = reinterpret_cast<const float4*>(hs)[qq];
        float4 w1 = wr4[qq + 1], x1 = reinterpret_cast<const float4*>(hs)[qq + 1];
        a0 += w0.x * x0.x + w0.y * x0.y + w0.z * x0.z + w0.w * x0.w;
        a1 += w1.x * x1.x + w1.y * x1.y + w1.z * x1.z + w1.w * x1.w;
    }
    out[j * OUTD + o] = g_bc[o] + a0 + a1;
}

// ---------------- launch ----------------
extern "C" void kernel_launch(void* const* d_in, const int* in_sizes, int n_in,
                              void* d_out, int out_size)
{
    const float* x   = (const float*)d_in[0];
    const float* Wih = (const float*)d_in[1];
    const float* Whh = (const float*)d_in[2];
    const float* bih = (const float*)d_in[3];
    const float* bhh = (const float*)d_in[4];
    const float* W1  = (const float*)d_in[5];
    const float* b1  = (const float*)d_in[6];
    const float* W2  = (const float*)d_in[7];
    const float* b2  = (const float*)d_in[8];
    float* out = (float*)d_out;

    xg_kernel<<<64, 512>>>(x, Wih, bih, bhh);
    mlp_precomp_kernel<<<16, 512>>>(W1, b1, W2, b2);
    lstm_scan_kernel<<<2, 256>>>(Whh);
    mlp_final_kernel<<<256, 64>>>(out);
}